// round 1
// baseline (speedup 1.0000x reference)
#include <cuda_runtime.h>
#include <math.h>

// ---------------------------------------------------------------------------
// AttentionBlock: B=8, S=2048, D=512, DOUT=512
//   q=x@Wq+bq; k=x@Wk+bk; v=x@Wv+bv
//   scores = q@k^T / sqrt(D); w = softmax(scores); att = w@v
//   out_nxt = LN(x+att)
//   h1 = LN(gelu(out_nxt + out_nxt@W1+b1))
//   h2 = LN(gelu(out_nxt + h1@W2+b2))
//   out = h2@W3+b3
// ---------------------------------------------------------------------------

#define BM 128
#define BN 128
#define BK 8
#define TST 132   // padded smem row stride (132*4B = 528B, 16B-aligned rows)

// Scratch (device globals; cudaMalloc is prohibited)
__device__ float g_q [16384 * 512];
__device__ float g_k [16384 * 512];
__device__ float g_v [16384 * 512];
__device__ float g_on[16384 * 512];
__device__ float g_t [16384 * 512];
__device__ float g_h [16384 * 512];
__device__ float g_s [8LL * 2048 * 2048];

// ---------------------------------------------------------------------------
// SGEMM: C = alpha * A@op(B) + bias, batched via blockIdx.z with strides.
// A: [M,K] row-major.  TB=false: B [K,N] row-major.  TB=true: B [N,K] row-major (A@B^T).
// All of M%128, N%128, K%8 are 0 for every call in this problem.
// ---------------------------------------------------------------------------
template <bool TB>
__global__ __launch_bounds__(256) void gemm_kernel(
    const float* __restrict__ A, const float* __restrict__ B,
    const float* __restrict__ bias, float* __restrict__ C,
    int M, int N, int K, float alpha,
    long long sA, long long sB, long long sC)
{
    __shared__ float As[BK][TST];
    __shared__ float Bs[BK][TST];

    const int bz = blockIdx.z;
    A += (long long)bz * sA;
    B += (long long)bz * sB;
    C += (long long)bz * sC;

    const int m0 = blockIdx.y * BM;
    const int n0 = blockIdx.x * BN;
    const int tid = threadIdx.x;
    const int tx = tid & 15;    // 0..15 -> 8 output cols each
    const int ty = tid >> 4;    // 0..15 -> 8 output rows each

    // A tile loader: 128 rows x 8 cols, one float4 per thread, transposed store
    const int ar = tid >> 1;
    const int ac = (tid & 1) * 4;
    const float* Aptr = A + (long long)(m0 + ar) * K + ac;

    // B tile loader
    int br, bc;
    const float* Bptr;
    if (TB) { br = tid >> 1; bc = (tid & 1) * 4;  Bptr = B + (long long)(n0 + br) * K + bc; }
    else    { br = tid >> 5; bc = (tid & 31) * 4; Bptr = B + (long long)br * N + n0 + bc; }

    float acc[8][8];
#pragma unroll
    for (int i = 0; i < 8; i++)
#pragma unroll
        for (int j = 0; j < 8; j++) acc[i][j] = 0.0f;

    for (int kt = 0; kt < K; kt += BK) {
        float4 av = *(const float4*)(Aptr + kt);
        As[ac + 0][ar] = av.x; As[ac + 1][ar] = av.y;
        As[ac + 2][ar] = av.z; As[ac + 3][ar] = av.w;

        if (TB) {
            float4 bv = *(const float4*)(Bptr + kt);
            Bs[bc + 0][br] = bv.x; Bs[bc + 1][br] = bv.y;
            Bs[bc + 2][br] = bv.z; Bs[bc + 3][br] = bv.w;
        } else {
            float4 bv = *(const float4*)(Bptr + (long long)kt * N);
            *(float4*)&Bs[br][bc] = bv;
        }
        __syncthreads();

#pragma unroll
        for (int k = 0; k < BK; k++) {
            float a[8], b[8];
            *(float4*)(a)     = *(const float4*)&As[k][ty * 8];
            *(float4*)(a + 4) = *(const float4*)&As[k][ty * 8 + 4];
            *(float4*)(b)     = *(const float4*)&Bs[k][tx * 8];
            *(float4*)(b + 4) = *(const float4*)&Bs[k][tx * 8 + 4];
#pragma unroll
            for (int i = 0; i < 8; i++)
#pragma unroll
                for (int j = 0; j < 8; j++)
                    acc[i][j] += a[i] * b[j];
        }
        __syncthreads();
    }

    // Epilogue: alpha + optional bias
#pragma unroll
    for (int i = 0; i < 8; i++) {
        const long long row = (long long)(m0 + ty * 8 + i) * N;
#pragma unroll
        for (int j = 0; j < 8; j++) {
            const int col = n0 + tx * 8 + j;
            float val = acc[i][j] * alpha;
            if (bias) val += bias[col];
            C[row + col] = val;
        }
    }
}

// ---------------------------------------------------------------------------
// Row softmax (in-place), rows of 2048, one block of 256 threads per row
// ---------------------------------------------------------------------------
__device__ __forceinline__ float warpMax(float v) {
#pragma unroll
    for (int o = 16; o > 0; o >>= 1) v = fmaxf(v, __shfl_xor_sync(0xffffffffu, v, o));
    return v;
}
__device__ __forceinline__ float warpSum(float v) {
#pragma unroll
    for (int o = 16; o > 0; o >>= 1) v += __shfl_xor_sync(0xffffffffu, v, o);
    return v;
}

__global__ __launch_bounds__(256) void softmax_kernel(float* __restrict__ S)
{
    float* p = S + (long long)blockIdx.x * 2048;
    const int tid = threadIdx.x;
    const int lane = tid & 31, wid = tid >> 5;
    __shared__ float sh[8];

    float v[8];
#pragma unroll
    for (int i = 0; i < 8; i++) v[i] = p[tid + i * 256];

    float m = v[0];
#pragma unroll
    for (int i = 1; i < 8; i++) m = fmaxf(m, v[i]);
    m = warpMax(m);
    if (lane == 0) sh[wid] = m;
    __syncthreads();
    m = sh[0];
#pragma unroll
    for (int w = 1; w < 8; w++) m = fmaxf(m, sh[w]);

    float e[8];
    float s = 0.0f;
#pragma unroll
    for (int i = 0; i < 8; i++) { e[i] = __expf(v[i] - m); s += e[i]; }
    s = warpSum(s);
    __syncthreads();
    if (lane == 0) sh[wid] = s;
    __syncthreads();
    float tot = 0.0f;
#pragma unroll
    for (int w = 0; w < 8; w++) tot += sh[w];
    const float inv = 1.0f / tot;

#pragma unroll
    for (int i = 0; i < 8; i++) p[tid + i * 256] = e[i] * inv;
}

// ---------------------------------------------------------------------------
// Row ops over D=512: one block of 128 threads per row, 4 elems/thread
//   MODE 0: O = LN(X + Y)
//   MODE 1: O = LN(gelu(X + Y))      (exact gelu via erf)
// ---------------------------------------------------------------------------
template <int MODE>
__global__ __launch_bounds__(128) void rowln_kernel(
    const float* __restrict__ X, const float* __restrict__ Y,
    const float* __restrict__ g, const float* __restrict__ b,
    float* __restrict__ O)
{
    const long long row = (long long)blockIdx.x * 512;
    const int tid = threadIdx.x;
    const int lane = tid & 31, wid = tid >> 5;
    __shared__ float s1[4], s2[4];

    float t[4];
    float sum = 0.0f, sq = 0.0f;
#pragma unroll
    for (int i = 0; i < 4; i++) {
        const int c = tid + i * 128;
        float u = X[row + c] + Y[row + c];
        if (MODE == 1) u = 0.5f * u * (1.0f + erff(u * 0.7071067811865476f));
        t[i] = u;
        sum += u;
        sq += u * u;
    }
    sum = warpSum(sum);
    sq = warpSum(sq);
    if (lane == 0) { s1[wid] = sum; s2[wid] = sq; }
    __syncthreads();
    float ts = 0.0f, tq = 0.0f;
#pragma unroll
    for (int w = 0; w < 4; w++) { ts += s1[w]; tq += s2[w]; }
    const float mean = ts * (1.0f / 512.0f);
    const float var = tq * (1.0f / 512.0f) - mean * mean;
    const float inv = rsqrtf(var + 1e-5f);

#pragma unroll
    for (int i = 0; i < 4; i++) {
        const int c = tid + i * 128;
        O[row + c] = (t[i] - mean) * inv * g[c] + b[c];
    }
}

// ---------------------------------------------------------------------------
// Host launcher
// ---------------------------------------------------------------------------
static float* symaddr(const void* sym)
{
    void* p = nullptr;
    cudaGetSymbolAddress(&p, sym);
    return (float*)p;
}

extern "C" void kernel_launch(void* const* d_in, const int* in_sizes, int n_in,
                              void* d_out, int out_size)
{
    const float* x    = (const float*)d_in[0];
    const float* Wq   = (const float*)d_in[1];
    const float* bq   = (const float*)d_in[2];
    const float* Wk   = (const float*)d_in[3];
    const float* bk   = (const float*)d_in[4];
    const float* Wv   = (const float*)d_in[5];
    const float* bv   = (const float*)d_in[6];
    const float* ln0g = (const float*)d_in[7];
    const float* ln0b = (const float*)d_in[8];
    const float* W1   = (const float*)d_in[9];
    const float* b1   = (const float*)d_in[10];
    const float* ln1g = (const float*)d_in[11];
    const float* ln1b = (const float*)d_in[12];
    const float* W2   = (const float*)d_in[13];
    const float* b2   = (const float*)d_in[14];
    const float* ln2g = (const float*)d_in[15];
    const float* ln2b = (const float*)d_in[16];
    const float* W3   = (const float*)d_in[17];
    const float* b3   = (const float*)d_in[18];
    float* out = (float*)d_out;

    float* q  = symaddr(g_q);
    float* k  = symaddr(g_k);
    float* v  = symaddr(g_v);
    float* on = symaddr(g_on);
    float* t  = symaddr(g_t);
    float* h  = symaddr(g_h);
    float* s  = symaddr(g_s);

    const int M = 16384;      // B*S
    const int D = 512;
    const int S = 2048;
    const long long sSD = (long long)S * D;       // per-batch q/k/v stride
    const long long sSS = (long long)S * S;       // per-batch scores stride
    const float scale = 0.044194173824159216f;    // 1/sqrt(512)

    dim3 gProj(4, 128, 1);    // N=512, M=16384
    dim3 gScores(16, 16, 8);  // N=2048, M=2048, batch 8
    dim3 gAtt(4, 16, 8);      // N=512,  M=2048, batch 8

    // QKV projections
    gemm_kernel<false><<<gProj, 256>>>(x, Wq, bq, q, M, D, D, 1.0f, 0, 0, 0);
    gemm_kernel<false><<<gProj, 256>>>(x, Wk, bk, k, M, D, D, 1.0f, 0, 0, 0);
    gemm_kernel<false><<<gProj, 256>>>(x, Wv, bv, v, M, D, D, 1.0f, 0, 0, 0);

    // scores = q @ k^T * (1/sqrt(D))   [per batch]
    gemm_kernel<true><<<gScores, 256>>>(q, k, nullptr, s, S, S, D, scale, sSD, sSD, sSS);

    // softmax over rows (in-place)
    softmax_kernel<<<16384, 256>>>(s);

    // att = w @ v   [per batch]
    gemm_kernel<false><<<gAtt, 256>>>(s, v, nullptr, t, S, D, S, 1.0f, sSS, sSD, sSD);

    // out_nxt = LN(x + att)
    rowln_kernel<0><<<16384, 128>>>(x, t, ln0g, ln0b, on);

    // h1 = LN(gelu(out_nxt + out_nxt@W1 + b1))
    gemm_kernel<false><<<gProj, 256>>>(on, W1, b1, t, M, D, D, 1.0f, 0, 0, 0);
    rowln_kernel<1><<<16384, 128>>>(on, t, ln1g, ln1b, h);

    // h2 = LN(gelu(out_nxt + h1@W2 + b2))   (reuse q as h2 buffer)
    gemm_kernel<false><<<gProj, 256>>>(h, W2, b2, t, M, D, D, 1.0f, 0, 0, 0);
    rowln_kernel<1><<<16384, 128>>>(on, t, ln2g, ln2b, q);

    // out = h2 @ W3 + b3
    gemm_kernel<false><<<gProj, 256>>>(q, W3, b3, out, M, D, D, 1.0f, 0, 0, 0);
}

// round 3
// speedup vs baseline: 2.3660x; 2.3660x over previous
#include <cuda_runtime.h>
#include <cuda_bf16.h>
#include <math.h>
#include <stdint.h>

// ===========================================================================
// AttentionBlock B=8,S=2048,D=512 — mma.sync bf16 3-product fp32-emulation
// (tcgen05 unavailable: harness PTX targets compute_103, not 103a)
// ===========================================================================

// ---------------- scratch (device globals; cudaMalloc prohibited) ----------
#define MTOT (16384 * 512)
__device__ __nv_bfloat16 g_xh[MTOT],  g_xl[MTOT];
__device__ __nv_bfloat16 g_qh[MTOT],  g_ql[MTOT];
__device__ __nv_bfloat16 g_kh[MTOT],  g_kl[MTOT];
__device__ __nv_bfloat16 g_vth[MTOT], g_vtl[MTOT];   // v^T per batch [512][2048]
__device__ __nv_bfloat16 g_onh[MTOT], g_onl[MTOT];
__device__ __nv_bfloat16 g_hh[MTOT],  g_hl[MTOT];    // h1
__device__ __nv_bfloat16 g_h2h[MTOT], g_h2l[MTOT];   // h2
__device__ __nv_bfloat16 g_sh[8LL * 2048 * 2048], g_sl[8LL * 2048 * 2048];
__device__ __nv_bfloat16 g_wth[6 * 512 * 512], g_wtl[6 * 512 * 512]; // W^T [N][K]
__device__ float g_v [MTOT];
__device__ float g_t [MTOT];
__device__ float g_on[MTOT];
__device__ float g_s [8LL * 2048 * 2048];

// ---------------- helpers ----------------
__device__ __forceinline__ uint32_t smem_u32(const void* p) {
    uint32_t a;
    asm("{ .reg .u64 t; cvta.to.shared.u64 t, %1; cvt.u32.u64 %0, t; }"
        : "=r"(a) : "l"(p));
    return a;
}
__device__ __forceinline__ void cpa16(uint32_t dst, const void* src) {
    asm volatile("cp.async.cg.shared.global [%0], [%1], 16;"
                 :: "r"(dst), "l"(src) : "memory");
}
#define CP_COMMIT() asm volatile("cp.async.commit_group;" ::: "memory")
#define CP_WAIT1()  asm volatile("cp.async.wait_group 1;"  ::: "memory")
#define CP_WAIT0()  asm volatile("cp.async.wait_group 0;"  ::: "memory")

#define MMA_B16(c, a0, a1, a2, a3, b0, b1)                                    \
    asm volatile("mma.sync.aligned.m16n8k16.row.col.f32.bf16.bf16.f32 "       \
        "{%0,%1,%2,%3}, {%4,%5,%6,%7}, {%8,%9}, {%0,%1,%2,%3};"               \
        : "+f"((c)[0]), "+f"((c)[1]), "+f"((c)[2]), "+f"((c)[3])              \
        : "r"(a0), "r"(a1), "r"(a2), "r"(a3), "r"(b0), "r"(b1))

// ---------------- GEMM ----------------
// C[M,N] = alpha * A@B + bias.  A planes: [M][K] bf16 hi/lo.  B planes: [N][K].
// OUTM=0: write fp32 C.  OUTM=1: write bf16 hi/lo split planes.
// BK=32; smem rows padded to 20 words (conflict-free for the frag pattern).
#define BKW 20
#define PLANE_W 2560            // 128 rows * 20 words
#define PLANE_B 10240           // bytes
#define BUF_B   40960           // 4 planes
#define GEMM_SMEM (2 * BUF_B)   // 81920

template <int OUTM>
__global__ __launch_bounds__(256, 2) void mma_gemm(
    const __nv_bfloat16* __restrict__ Ah, const __nv_bfloat16* __restrict__ Al,
    const __nv_bfloat16* __restrict__ Bh, const __nv_bfloat16* __restrict__ Bl,
    const float* __restrict__ bias,
    float* __restrict__ Cf, __nv_bfloat16* __restrict__ Ch, __nv_bfloat16* __restrict__ Cl,
    int N, int K, float alpha,
    long long sA, long long sB, long long sC)
{
    extern __shared__ uint32_t sm[];
    const uint32_t sbase = smem_u32(sm);

    const int bz = blockIdx.z;
    Ah += (long long)bz * sA;  Al += (long long)bz * sA;
    Bh += (long long)bz * sB;  Bl += (long long)bz * sB;

    const int m0 = blockIdx.y * 128;
    const int n0 = blockIdx.x * 128;
    const int tid  = threadIdx.x;
    const int wid  = tid >> 5, lane = tid & 31;
    const int wm   = wid >> 2, wn = wid & 3;      // warp tile: 64 x 32
    const int g    = lane >> 2, t = lane & 3;

    // loader geometry: 2 threads per row, 2x16B segments each
    const int lrow = tid >> 1;
    const int lseg = (tid & 1) * 2;
    const char* gAh = (const char*)(Ah + (long long)(m0 + lrow) * K) + lseg * 16;
    const char* gAl = (const char*)(Al + (long long)(m0 + lrow) * K) + lseg * 16;
    const char* gBh = (const char*)(Bh + (long long)(n0 + lrow) * K) + lseg * 16;
    const char* gBl = (const char*)(Bl + (long long)(n0 + lrow) * K) + lseg * 16;
    const uint32_t dst0 = sbase + lrow * 80 + lseg * 16;

    float acc[4][4][4];
#pragma unroll
    for (int i = 0; i < 4; i++)
#pragma unroll
        for (int j = 0; j < 4; j++)
#pragma unroll
            for (int e = 0; e < 4; e++) acc[i][j][e] = 0.0f;

    const int NCH = K >> 5;

    // prefetch chunk 0 into buffer 0
    {
        cpa16(dst0,              gAh); cpa16(dst0 + 16,              gAh + 16);
        cpa16(dst0 + PLANE_B,    gAl); cpa16(dst0 + PLANE_B + 16,    gAl + 16);
        cpa16(dst0 + 2*PLANE_B,  gBh); cpa16(dst0 + 2*PLANE_B + 16,  gBh + 16);
        cpa16(dst0 + 3*PLANE_B,  gBl); cpa16(dst0 + 3*PLANE_B + 16,  gBl + 16);
        CP_COMMIT();
    }

    for (int ch = 0; ch < NCH; ch++) {
        if (ch + 1 < NCH) {
            const long long co = (long long)(ch + 1) * 64;
            const uint32_t d = dst0 + ((ch + 1) & 1) * BUF_B;
            cpa16(d,              gAh + co); cpa16(d + 16,              gAh + co + 16);
            cpa16(d + PLANE_B,    gAl + co); cpa16(d + PLANE_B + 16,    gAl + co + 16);
            cpa16(d + 2*PLANE_B,  gBh + co); cpa16(d + 2*PLANE_B + 16,  gBh + co + 16);
            cpa16(d + 3*PLANE_B,  gBl + co); cpa16(d + 3*PLANE_B + 16,  gBl + co + 16);
            CP_COMMIT();
            CP_WAIT1();
        } else {
            CP_WAIT0();
        }
        __syncthreads();

        const uint32_t* Sb  = sm + (ch & 1) * (BUF_B / 4);
        const uint32_t* AhS = Sb;
        const uint32_t* AlS = Sb + PLANE_W;
        const uint32_t* BhS = Sb + 2 * PLANE_W;
        const uint32_t* BlS = Sb + 3 * PLANE_W;

        const int abase = (wm * 64 + g) * BKW + t;
        const int bbase = (wn * 32 + g) * BKW + t;

#pragma unroll
        for (int ks = 0; ks < 2; ks++) {
            const int ko = ks * 8;
            uint32_t bh[4][2], bl[4][2];
#pragma unroll
            for (int ni = 0; ni < 4; ni++) {
                const int o = bbase + ni * 160 + ko;
                bh[ni][0] = BhS[o]; bh[ni][1] = BhS[o + 4];
                bl[ni][0] = BlS[o]; bl[ni][1] = BlS[o + 4];
            }
#pragma unroll
            for (int mi = 0; mi < 4; mi++) {
                const int o = abase + mi * 320 + ko;
                const uint32_t ah0 = AhS[o],       ah1 = AhS[o + 160];
                const uint32_t ah2 = AhS[o + 4],   ah3 = AhS[o + 164];
                const uint32_t al0 = AlS[o],       al1 = AlS[o + 160];
                const uint32_t al2 = AlS[o + 4],   al3 = AlS[o + 164];
#pragma unroll
                for (int ni = 0; ni < 4; ni++) {
                    MMA_B16(acc[mi][ni], ah0, ah1, ah2, ah3, bh[ni][0], bh[ni][1]);
                    MMA_B16(acc[mi][ni], al0, al1, al2, al3, bh[ni][0], bh[ni][1]);
                    MMA_B16(acc[mi][ni], ah0, ah1, ah2, ah3, bl[ni][0], bl[ni][1]);
                }
            }
        }
        __syncthreads();
    }

    // ---------------- epilogue ----------------
    float* CfB = Cf + (long long)bz * sC;
    __nv_bfloat16* ChB = Ch + (long long)bz * sC;
    __nv_bfloat16* ClB = Cl + (long long)bz * sC;

#pragma unroll
    for (int mi = 0; mi < 4; mi++) {
#pragma unroll
        for (int ni = 0; ni < 4; ni++) {
            const int r0 = m0 + wm * 64 + mi * 16 + g;
            const int c  = n0 + wn * 32 + ni * 8 + t * 2;
            float v0 = acc[mi][ni][0] * alpha, v1 = acc[mi][ni][1] * alpha;
            float v2 = acc[mi][ni][2] * alpha, v3 = acc[mi][ni][3] * alpha;
            if (bias) {
                const float b0 = bias[c], b1 = bias[c + 1];
                v0 += b0; v1 += b1; v2 += b0; v3 += b1;
            }
            if (OUTM == 0) {
                float2 p0 = make_float2(v0, v1);
                float2 p1 = make_float2(v2, v3);
                *(float2*)&CfB[(long long)r0 * N + c]       = p0;
                *(float2*)&CfB[(long long)(r0 + 8) * N + c] = p1;
            } else {
                __nv_bfloat162 h0 = __floats2bfloat162_rn(v0, v1);
                __nv_bfloat162 l0 = __floats2bfloat162_rn(
                    v0 - __bfloat162float(h0.x), v1 - __bfloat162float(h0.y));
                __nv_bfloat162 h1 = __floats2bfloat162_rn(v2, v3);
                __nv_bfloat162 l1 = __floats2bfloat162_rn(
                    v2 - __bfloat162float(h1.x), v3 - __bfloat162float(h1.y));
                ((__nv_bfloat162*)ChB)[((long long)r0 * N + c) >> 1]       = h0;
                ((__nv_bfloat162*)ClB)[((long long)r0 * N + c) >> 1]       = l0;
                ((__nv_bfloat162*)ChB)[((long long)(r0 + 8) * N + c) >> 1] = h1;
                ((__nv_bfloat162*)ClB)[((long long)(r0 + 8) * N + c) >> 1] = l1;
            }
        }
    }
}

// ---------------- split (fp32 -> bf16 hi/lo), elementwise ----------------
__global__ __launch_bounds__(256) void split_kernel(
    const float* __restrict__ in, __nv_bfloat16* __restrict__ oh,
    __nv_bfloat16* __restrict__ ol, int n4)
{
    const int i = blockIdx.x * 256 + threadIdx.x;
    if (i >= n4) return;
    float4 v = ((const float4*)in)[i];
    __nv_bfloat162 h0 = __floats2bfloat162_rn(v.x, v.y);
    __nv_bfloat162 h1 = __floats2bfloat162_rn(v.z, v.w);
    __nv_bfloat162 l0 = __floats2bfloat162_rn(v.x - __bfloat162float(h0.x),
                                              v.y - __bfloat162float(h0.y));
    __nv_bfloat162 l1 = __floats2bfloat162_rn(v.z - __bfloat162float(h1.x),
                                              v.w - __bfloat162float(h1.y));
    ((__nv_bfloat162*)oh)[i * 2]     = h0;
    ((__nv_bfloat162*)oh)[i * 2 + 1] = h1;
    ((__nv_bfloat162*)ol)[i * 2]     = l0;
    ((__nv_bfloat162*)ol)[i * 2 + 1] = l1;
}

// ------------- transpose + split: in fp32 [R][C] -> planes [C][R] ----------
__global__ __launch_bounds__(256) void tsplit_kernel(
    const float* __restrict__ in, __nv_bfloat16* __restrict__ oh,
    __nv_bfloat16* __restrict__ ol, int R, int C,
    long long sI, long long sO)
{
    __shared__ float tile[32][33];
    const int z = blockIdx.z;
    in += (long long)z * sI;
    oh += (long long)z * sO;
    ol += (long long)z * sO;
    const int c0 = blockIdx.x * 32, r0 = blockIdx.y * 32;
    const int tx = threadIdx.x & 31, ty = threadIdx.x >> 5;   // 32 x 8

#pragma unroll
    for (int i = 0; i < 4; i++)
        tile[ty + i * 8][tx] = in[(long long)(r0 + ty + i * 8) * C + c0 + tx];
    __syncthreads();
#pragma unroll
    for (int i = 0; i < 4; i++) {
        const float v = tile[tx][ty + i * 8];
        const __nv_bfloat16 h = __float2bfloat16(v);
        const long long o = (long long)(c0 + ty + i * 8) * R + r0 + tx;
        oh[o] = h;
        ol[o] = __float2bfloat16(v - __bfloat162float(h));
    }
}

// ---------------- softmax (fp32 in, split bf16 out) ----------------
__device__ __forceinline__ float warpMax(float v) {
#pragma unroll
    for (int o = 16; o > 0; o >>= 1) v = fmaxf(v, __shfl_xor_sync(0xffffffffu, v, o));
    return v;
}
__device__ __forceinline__ float warpSum(float v) {
#pragma unroll
    for (int o = 16; o > 0; o >>= 1) v += __shfl_xor_sync(0xffffffffu, v, o);
    return v;
}

__global__ __launch_bounds__(256) void softmax_kernel(
    const float* __restrict__ S, __nv_bfloat16* __restrict__ oh,
    __nv_bfloat16* __restrict__ ol)
{
    const long long base = (long long)blockIdx.x * 2048;
    const float* p = S + base;
    const int tid = threadIdx.x;
    const int lane = tid & 31, wid = tid >> 5;
    __shared__ float sh[8];

    float v[8];
#pragma unroll
    for (int i = 0; i < 8; i++) v[i] = p[tid + i * 256];

    float m = v[0];
#pragma unroll
    for (int i = 1; i < 8; i++) m = fmaxf(m, v[i]);
    m = warpMax(m);
    if (lane == 0) sh[wid] = m;
    __syncthreads();
    m = sh[0];
#pragma unroll
    for (int w = 1; w < 8; w++) m = fmaxf(m, sh[w]);

    float e[8];
    float s = 0.0f;
#pragma unroll
    for (int i = 0; i < 8; i++) { e[i] = __expf(v[i] - m); s += e[i]; }
    s = warpSum(s);
    __syncthreads();
    if (lane == 0) sh[wid] = s;
    __syncthreads();
    float tot = 0.0f;
#pragma unroll
    for (int w = 0; w < 8; w++) tot += sh[w];
    const float inv = 1.0f / tot;

#pragma unroll
    for (int i = 0; i < 8; i++) {
        const float val = e[i] * inv;
        const __nv_bfloat16 h = __float2bfloat16(val);
        oh[base + tid + i * 256] = h;
        ol[base + tid + i * 256] = __float2bfloat16(val - __bfloat162float(h));
    }
}

// ---------------- fused add(+gelu)+LN, split bf16 out (+optional fp32) -----
template <int MODE, bool WF32>
__global__ __launch_bounds__(128) void rowln_kernel(
    const float* __restrict__ X, const float* __restrict__ Y,
    const float* __restrict__ g, const float* __restrict__ b,
    float* __restrict__ Of, __nv_bfloat16* __restrict__ Oh,
    __nv_bfloat16* __restrict__ Ol)
{
    const long long row = (long long)blockIdx.x * 512;
    const int tid = threadIdx.x;
    const int lane = tid & 31, wid = tid >> 5;
    __shared__ float s1[4], s2[4];

    float t[4];
    float sum = 0.0f, sq = 0.0f;
#pragma unroll
    for (int i = 0; i < 4; i++) {
        const int c = tid + i * 128;
        float u = X[row + c] + Y[row + c];
        if (MODE == 1) u = 0.5f * u * (1.0f + erff(u * 0.7071067811865476f));
        t[i] = u;
        sum += u;
        sq += u * u;
    }
    sum = warpSum(sum);
    sq = warpSum(sq);
    if (lane == 0) { s1[wid] = sum; s2[wid] = sq; }
    __syncthreads();
    float ts = 0.0f, tq = 0.0f;
#pragma unroll
    for (int w = 0; w < 4; w++) { ts += s1[w]; tq += s2[w]; }
    const float mean = ts * (1.0f / 512.0f);
    const float var = tq * (1.0f / 512.0f) - mean * mean;
    const float inv = rsqrtf(var + 1e-5f);

#pragma unroll
    for (int i = 0; i < 4; i++) {
        const int c = tid + i * 128;
        const float o = (t[i] - mean) * inv * g[c] + b[c];
        if (WF32) Of[row + c] = o;
        const __nv_bfloat16 h = __float2bfloat16(o);
        Oh[row + c] = h;
        Ol[row + c] = __float2bfloat16(o - __bfloat162float(h));
    }
}

// ---------------- host ----------------
template <typename T>
static T* symaddr(const void* sym)
{
    void* p = nullptr;
    cudaGetSymbolAddress(&p, sym);
    return (T*)p;
}

extern "C" void kernel_launch(void* const* d_in, const int* in_sizes, int n_in,
                              void* d_out, int out_size)
{
    const float* x    = (const float*)d_in[0];
    const float* Wq   = (const float*)d_in[1];
    const float* bq   = (const float*)d_in[2];
    const float* Wk   = (const float*)d_in[3];
    const float* bk   = (const float*)d_in[4];
    const float* Wv   = (const float*)d_in[5];
    const float* bv   = (const float*)d_in[6];
    const float* ln0g = (const float*)d_in[7];
    const float* ln0b = (const float*)d_in[8];
    const float* W1   = (const float*)d_in[9];
    const float* b1   = (const float*)d_in[10];
    const float* ln1g = (const float*)d_in[11];
    const float* ln1b = (const float*)d_in[12];
    const float* W2   = (const float*)d_in[13];
    const float* b2   = (const float*)d_in[14];
    const float* ln2g = (const float*)d_in[15];
    const float* ln2b = (const float*)d_in[16];
    const float* W3   = (const float*)d_in[17];
    const float* b3   = (const float*)d_in[18];
    float* out = (float*)d_out;

    typedef __nv_bfloat16 bf;
    bf* xh  = symaddr<bf>(g_xh);   bf* xl  = symaddr<bf>(g_xl);
    bf* qh  = symaddr<bf>(g_qh);   bf* ql  = symaddr<bf>(g_ql);
    bf* kh  = symaddr<bf>(g_kh);   bf* kl  = symaddr<bf>(g_kl);
    bf* vth = symaddr<bf>(g_vth);  bf* vtl = symaddr<bf>(g_vtl);
    bf* onh = symaddr<bf>(g_onh);  bf* onl = symaddr<bf>(g_onl);
    bf* hh  = symaddr<bf>(g_hh);   bf* hl  = symaddr<bf>(g_hl);
    bf* h2h = symaddr<bf>(g_h2h);  bf* h2l = symaddr<bf>(g_h2l);
    bf* sh_ = symaddr<bf>(g_sh);   bf* sl_ = symaddr<bf>(g_sl);
    bf* wth = symaddr<bf>(g_wth);  bf* wtl = symaddr<bf>(g_wtl);
    float* v  = symaddr<float>(g_v);
    float* tt = symaddr<float>(g_t);
    float* on = symaddr<float>(g_on);
    float* s  = symaddr<float>(g_s);

    cudaFuncSetAttribute(mma_gemm<0>, cudaFuncAttributeMaxDynamicSharedMemorySize, GEMM_SMEM);
    cudaFuncSetAttribute(mma_gemm<1>, cudaFuncAttributeMaxDynamicSharedMemorySize, GEMM_SMEM);

    const long long sSD = 2048LL * 512;
    const long long sSS = 2048LL * 2048;
    const long long WSZ = 512LL * 512;
    const float scale = 0.044194173824159216f;   // 1/sqrt(512)

    // 1) split x
    split_kernel<<<MTOT / 1024, 256>>>(x, xh, xl, MTOT / 4);

    // 2) transpose-split weights [K][N] -> [N][K]
    dim3 gW(16, 16, 1);
    dim3 bT(256);
    tsplit_kernel<<<gW, bT>>>(Wq, wth + 0 * WSZ, wtl + 0 * WSZ, 512, 512, 0, 0);
    tsplit_kernel<<<gW, bT>>>(Wk, wth + 1 * WSZ, wtl + 1 * WSZ, 512, 512, 0, 0);
    tsplit_kernel<<<gW, bT>>>(Wv, wth + 2 * WSZ, wtl + 2 * WSZ, 512, 512, 0, 0);
    tsplit_kernel<<<gW, bT>>>(W1, wth + 3 * WSZ, wtl + 3 * WSZ, 512, 512, 0, 0);
    tsplit_kernel<<<gW, bT>>>(W2, wth + 4 * WSZ, wtl + 4 * WSZ, 512, 512, 0, 0);
    tsplit_kernel<<<gW, bT>>>(W3, wth + 5 * WSZ, wtl + 5 * WSZ, 512, 512, 0, 0);

    dim3 gProj(4, 128, 1);     // N=512, M=16384
    dim3 gScores(16, 16, 8);   // N=2048, M=2048 per batch
    dim3 gAtt(4, 16, 8);

    // 3) q, k (split out), v (fp32 out)
    mma_gemm<1><<<gProj, 256, GEMM_SMEM>>>(xh, xl, wth + 0 * WSZ, wtl + 0 * WSZ,
        bq, nullptr, qh, ql, 512, 512, 1.0f, 0, 0, 0);
    mma_gemm<1><<<gProj, 256, GEMM_SMEM>>>(xh, xl, wth + 1 * WSZ, wtl + 1 * WSZ,
        bk, nullptr, kh, kl, 512, 512, 1.0f, 0, 0, 0);
    mma_gemm<0><<<gProj, 256, GEMM_SMEM>>>(xh, xl, wth + 2 * WSZ, wtl + 2 * WSZ,
        bv, v, nullptr, nullptr, 512, 512, 1.0f, 0, 0, 0);

    // 4) v -> v^T planes (per batch)
    tsplit_kernel<<<dim3(16, 64, 8), bT>>>(v, vth, vtl, 2048, 512, sSD, sSD);

    // 5) scores = q @ k^T * scale (fp32 out)
    mma_gemm<0><<<gScores, 256, GEMM_SMEM>>>(qh, ql, kh, kl,
        nullptr, s, nullptr, nullptr, 2048, 512, scale, sSD, sSD, sSS);

    // 6) softmax -> split planes
    softmax_kernel<<<16384, 256>>>(s, sh_, sl_);

    // 7) att = w @ v (fp32 out)
    mma_gemm<0><<<gAtt, 256, GEMM_SMEM>>>(sh_, sl_, vth, vtl,
        nullptr, tt, nullptr, nullptr, 512, 2048, 1.0f, sSS, sSD, sSD);

    // 8) out_nxt = LN(x + att): fp32 + split
    rowln_kernel<0, true><<<16384, 128>>>(x, tt, ln0g, ln0b, on, onh, onl);

    // 9) h1 = LN(gelu(on + on@W1 + b1)): split only
    mma_gemm<0><<<gProj, 256, GEMM_SMEM>>>(onh, onl, wth + 3 * WSZ, wtl + 3 * WSZ,
        b1, tt, nullptr, nullptr, 512, 512, 1.0f, 0, 0, 0);
    rowln_kernel<1, false><<<16384, 128>>>(on, tt, ln1g, ln1b, nullptr, hh, hl);

    // 10) h2 = LN(gelu(on + h1@W2 + b2)): split only
    mma_gemm<0><<<gProj, 256, GEMM_SMEM>>>(hh, hl, wth + 4 * WSZ, wtl + 4 * WSZ,
        b2, tt, nullptr, nullptr, 512, 512, 1.0f, 0, 0, 0);
    rowln_kernel<1, false><<<16384, 128>>>(on, tt, ln2g, ln2b, nullptr, h2h, h2l);

    // 11) out = h2 @ W3 + b3 (fp32 out)
    mma_gemm<0><<<gProj, 256, GEMM_SMEM>>>(h2h, h2l, wth + 5 * WSZ, wtl + 5 * WSZ,
        b3, out, nullptr, nullptr, 512, 512, 1.0f, 0, 0, 0);
}